// round 8
// baseline (speedup 1.0000x reference)
#include <cuda_runtime.h>
#include <cuda_bf16.h>

// N=131072 rows, output (N,4) f32. JAX bisection bbox relabel, BETA=1.
// R8: fused single kernel (R7 structure) + speculative 2-bit bisection rounds:
// each round evaluates m1,m2,m3 in parallel (ILP) and applies two halvings,
// bitwise-identical to two sequential bisection steps. 17 rounds == 34 iters.
// Slot-phase latency chain roughly halves (it was the limiter: ~1 active
// slot-warp per block stuck on a ~60cyc/iter dependency chain).

#define NROWS 131072
#define TOTAL (2 * NROWS)
#define BLOCK 256
#define ROUNDS 17                     // 2 halvings per round = 34 iters
#define E_F 2.718281828459045f
#define INV_E_F 0.36787944117144233f
#define SMALL_TH 5.656854249492380f   // 4*sqrt(2)

// flag bits
#define F_ISC    1
#define F_RLL    2     // r/l: left mode
#define F_HASB   4
#define F_SMALL  8
#define F_SB1    16    // C: B side is side1
#define F_SB2    32
#define F_SA1    64    // C: A side is side1
#define F_SA2    128

__device__ __forceinline__ float smooth_l1(float x) {
    float d = fabsf(x);
    return d < 1.0f ? 0.5f * d * d : d - 0.5f;
}
__device__ __forceinline__ float eps_val(float w, float wh, float lwp) {
    return smooth_l1((w - wh) * 0.5f) + smooth_l1(logf(fmaxf(w, 1e-12f)) - lwp);
}

// Sign-carrying eval of eps_prime * max(w,1e-12) without log (clip saturates
// outside [wpc/e, e*wpc]; inside, sign(t+log(mh/wpc)) == sign(mh*e^t - wpc):
// one MUFU.EX2, derivative bounded below -> no amplification). sigma: flip at m<0.
__device__ __forceinline__ float bis_g(float m, float wh, float wpc,
                                       float hi, float lo, bool sigma) {
    float mh = fmaxf(m, 1e-12f);
    float cA = fminf(fmaxf((m - wh) * 0.5f, -1.0f), 1.0f);
    float t  = 0.5f * cA * mh;
    float g;
    if (mh >= hi)      g = t + 1.0f;
    else if (mh <= lo) g = t - 1.0f;
    else               g = fmaf(mh, __expf(t), -wpc);
    if (sigma && m < 0.0f) g = -g;
    return g;
}

struct Slot { float u, v, u0, v0, wh, wpc, hi, lo; bool sig; };

__device__ __forceinline__ void slot_init(Slot& s, float u0, float v0,
                                          float wh, float wpc, bool sig) {
    s.u = s.u0 = u0; s.v = s.v0 = v0; s.wh = wh; s.wpc = wpc;
    s.hi = E_F * wpc; s.lo = INV_E_F * wpc; s.sig = sig;
}

// One speculative round = two exact bisection halvings.
__device__ __forceinline__ void slot_round(Slot& s) {
    float m2 = (s.u + s.v) * 0.5f;
    float m1 = (s.u + m2) * 0.5f;
    float m3 = (m2 + s.v) * 0.5f;
    bool c1 = bis_g(m1, s.wh, s.wpc, s.hi, s.lo, s.sig) >= 0.0f;
    bool c2 = bis_g(m2, s.wh, s.wpc, s.hi, s.lo, s.sig) >= 0.0f;
    bool c3 = bis_g(m3, s.wh, s.wpc, s.hi, s.lo, s.sig) >= 0.0f;
    float nu = c2 ? (c1 ? s.u : m1) : (c3 ? m2 : m3);
    float nv = c2 ? (c1 ? m1 : m2) : (c3 ? m3 : s.v);
    s.u = nu; s.v = nv;
}
__device__ __forceinline__ float slot_result(const Slot& s) {
    float m  = (s.u + s.v) * 0.5f;
    float fu = bis_g(s.u0, s.wh, s.wpc, s.hi, s.lo, s.sig);
    float fv = bis_g(s.v0, s.wh, s.wpc, s.hi, s.lo, s.sig);
    return (fu >= 0.0f) ? s.u0 : ((fv <= 0.0f) ? s.v0 : m);
}

// branchB slot k of {c2, c3, c4|c5, c6}: shared (wp, wh, w0).
__device__ __forceinline__ void initB_k(Slot& s, int k, float wp, float wh,
                                        float w0) {
    float wpc = fmaxf(wp, 1e-12f);
    float base = fmaxf(w0, fmaxf(wh - 2.0f, E_F * wp));
    float disc = sqrtf(fmaxf(1.0f - 32.0f / fmaxf(wh * wh, 1e-12f), 0.0f));
    float ebwp = E_F * wp;
    bool smallB = (wh <= SMALL_TH);
    float u, v; bool sig;
    if (k == 0)      { u = fmaxf(w0, wp);     v = fminf(ebwp, wh); sig = false; }  // c2
    else if (k == 1) { u = fmaxf(base, 2.0f); v = wh;              sig = false; }  // c3
    else if (k == 2) {
        if (smallB) { u = base; v = fminf(E_F, wh); }                              // c4
        else        { u = base; v = fminf(fminf(ebwp, wh), wh * 0.25f * (1.0f + disc)); } // c5
        sig = true;
    } else {
        u = fmaxf(base, wh * 0.25f * (1.0f - disc));                               // c6
        v = fminf(ebwp, wh);
        sig = true;
    }
    slot_init(s, u, v, wh, wpc, sig);
}

__global__ void __launch_bounds__(BLOCK) k_fused(
        const float* __restrict__ pred,
        const float* __restrict__ target,
        const float* __restrict__ crop,
        const float* __restrict__ prop,
        const int*   __restrict__ cases,
        float*       __restrict__ out) {
    __shared__ int   s_cnt, s_nslots;
    __shared__ int   s_flags[BLOCK];
    __shared__ int   s_task[BLOCK];          // global task id t
    __shared__ float s_wp[BLOCK], s_whB[BLOCK], s_whA[BLOCK], s_w0[BLOCK];
    __shared__ float s_p1[BLOCK], s_p2[BLOCK];     // a1,b1 (r/l) or a2,b2 (C)
    __shared__ float s_wh1[BLOCK], s_wh2[BLOCK];   // C only
    __shared__ short s_desc[BLOCK * 5];            // (local<<3)|k  (k=0..3 B, 4=A)
    __shared__ float s_res[BLOCK * 5];

    int tid = threadIdx.x;
    if (tid == 0) { s_cnt = 0; s_nslots = 0; }
    __syncthreads();

    // ---------------- phase 1: classify + trivial resolve ----------------
    int t = blockIdx.x * BLOCK + tid;
    {
        int i = t >> 1, a = t & 1;
        int lt = cases[i * 4 + 2 * a + 0];
        int rb = cases[i * 4 + 2 * a + 1];
        int type = (lt ? 2 : 0) | (rb ? 1 : 0);   // 0=none 1=r 2=l 3=both

        if (type == 0) {
            out[i * 4 + a]     = target[i * 4 + a];
            out[i * 4 + 2 + a] = expf(target[i * 4 + 2 + a]);
        } else {
            float pd = pred[i * 4 + a];
            float td = target[i * 4 + a];
            float to = expf(target[i * 4 + 2 + a]);
            float p_d = prop[i * 4 + a];
            float p_o = prop[i * 4 + 2 + a];
            float ca = 0.5f * (p_d + p_o);
            float da = p_o - p_d;
            float cropa = crop[i * 4 + a];

            if (type != 3) {
                float po = expf(pred[i * 4 + 2 + a]);
                float a1, b1, wh;
                if (type == 1) { a1 = td - 0.5f * to; b1 = (cropa - ca) / da; wh = 2.0f * (pd - a1); }
                else           { a1 = -ca / da;       b1 = td + 0.5f * to;   wh = 2.0f * (b1 - pd); }
                float w0 = b1 - a1;
                bool bA = fmaxf(w0, wh) < po;
                bool bB = fmaxf(w0, po) < wh;
                if (!bA && !bB) {
                    float d = (type == 1) ? (a1 + 0.5f * w0) : (b1 - 0.5f * w0);
                    out[i * 4 + a]     = d;
                    out[i * 4 + 2 + a] = w0;
                } else {
                    int L = atomicAdd(&s_cnt, 1);
                    int fl = (type == 2 ? F_RLL : 0);
                    s_task[L] = t;
                    s_wp[L] = po; s_w0[L] = w0;
                    s_p1[L] = a1; s_p2[L] = b1;
                    int ns, base;
                    if (bA) {
                        s_whA[L] = wh;
                        ns = 1;
                        base = atomicAdd(&s_nslots, ns);
                        s_desc[base] = (short)((L << 3) | 4);
                    } else {
                        fl |= F_HASB;
                        bool sm = (wh <= SMALL_TH);
                        if (sm) fl |= F_SMALL;
                        s_whB[L] = wh;
                        ns = sm ? 3 : 4;
                        base = atomicAdd(&s_nslots, ns);
                        for (int k = 0; k < ns; k++)
                            s_desc[base + k] = (short)((L << 3) | k);
                    }
                    s_flags[L] = fl;
                }
            } else {
                float a2 = -ca / da;
                float b2 = (cropa - ca) / da;
                float wh1 = 2.0f * (pd - a2);
                float wh2 = 2.0f * (b2 - pd);
                if (pd >= fmaxf(wh1, wh2)) {          // trivial (wp = dp = pd)
                    out[i * 4 + a]     = pd;
                    out[i * 4 + 2 + a] = pd;
                } else {
                    float w0 = b2 - a2;
                    bool A1 = fmaxf(w0, wh1) < pd, B1 = fmaxf(w0, pd) < wh1;
                    bool A2 = fmaxf(w0, wh2) < pd, B2 = fmaxf(w0, pd) < wh2;
                    if (!(A1 | B1 | A2 | B2)) {       // both sides -> w0
                        float lwp = logf(fmaxf(pd, 1e-12f));
                        bool pick1 = eps_val(w0, wh1, lwp) <= eps_val(w0, wh2, lwp);
                        float d = pick1 ? (a2 + 0.5f * w0) : (b2 + 0.5f * w0);
                        out[i * 4 + a]     = d;
                        out[i * 4 + 2 + a] = w0;
                    } else {
                        int L = atomicAdd(&s_cnt, 1);
                        int fl = F_ISC;
                        int sb = B1 ? 1 : (B2 ? 2 : 0);   // at most one B side
                        int sa = A1 ? 1 : (A2 ? 2 : 0);
                        if (sb == 1) fl |= F_SB1; else if (sb == 2) fl |= F_SB2;
                        if (sa == 1) fl |= F_SA1; else if (sa == 2) fl |= F_SA2;
                        float whB = (sb == 1) ? wh1 : wh2;
                        float whA = (sa == 1) ? wh1 : wh2;
                        s_task[L] = t;
                        s_wp[L] = pd; s_w0[L] = w0;
                        s_p1[L] = a2; s_p2[L] = b2;
                        s_wh1[L] = wh1; s_wh2[L] = wh2;
                        s_whA[L] = whA; s_whB[L] = whB;
                        int nb = 0;
                        bool sm = (whB <= SMALL_TH);
                        if (sb) { fl |= F_HASB; if (sm) fl |= F_SMALL; nb = sm ? 3 : 4; }
                        int ns = nb + (sa ? 1 : 0);
                        int base = atomicAdd(&s_nslots, ns);
                        for (int k = 0; k < nb; k++)
                            s_desc[base + k] = (short)((L << 3) | k);
                        if (sa) s_desc[base + nb] = (short)((L << 3) | 4);
                        s_flags[L] = fl;
                    }
                }
            }
        }
    }
    __syncthreads();

    // ---------------- phase 2: slot-parallel speculative bisection --------
    int nslots = s_nslots;
    for (int sidx = tid; sidx < nslots; sidx += BLOCK) {
        int d = s_desc[sidx];
        int L = d >> 3, k = d & 7;
        float wp = s_wp[L], w0 = s_w0[L];
        Slot sl;
        if (k == 4) {
            float wh = s_whA[L];
            slot_init(sl, fmaxf(w0, wh), wp, wh, fmaxf(wp, 1e-12f), false);
        } else {
            initB_k(sl, k, wp, s_whB[L], w0);
        }
#pragma unroll 1
        for (int r = 0; r < ROUNDS; r++) slot_round(sl);
        s_res[L * 5 + k] = slot_result(sl);
    }
    __syncthreads();

    // ---------------- phase 3: finalize -----------------------------------
    int cnt = s_cnt;
    if (tid < cnt) {
        int L = tid;
        int fl = s_flags[L];
        int tg = s_task[L];
        int i = tg >> 1, a = tg & 1;
        float wp = s_wp[L], w0 = s_w0[L];
        float lwp = logf(fmaxf(wp, 1e-12f));

        float bw = w0;
        if (fl & F_HASB) {
            float whB = s_whB[L];
            bool sm = (fl & F_SMALL);
            float bv = eps_val(w0, whB, lwp);
            float e1 = eps_val(whB, whB, lwp);
            if (e1 < bv) { bv = e1; bw = whB; }
            float e2 = eps_val(s_res[L * 5 + 0], whB, lwp);
            if (e2 < bv) { bv = e2; bw = s_res[L * 5 + 0]; }
            float e3 = eps_val(s_res[L * 5 + 1], whB, lwp);
            if (e3 < bv) { bv = e3; bw = s_res[L * 5 + 1]; }
            float e4 = eps_val(s_res[L * 5 + 2], whB, lwp);
            if (e4 < bv) { bv = e4; bw = s_res[L * 5 + 2]; }
            if (!sm) {
                float e5 = eps_val(s_res[L * 5 + 3], whB, lwp);
                if (e5 < bv) { bv = e5; bw = s_res[L * 5 + 3]; }
            }
        }

        float dres, wres;
        if (!(fl & F_ISC)) {
            wres = (fl & F_HASB) ? bw : s_res[L * 5 + 4];
            float a1 = s_p1[L], b1 = s_p2[L];
            dres = (fl & F_RLL) ? (b1 - 0.5f * wres) : (a1 + 0.5f * wres);
        } else {
            float a2 = s_p1[L], b2 = s_p2[L];
            float wh1 = s_wh1[L], wh2 = s_wh2[L];
            int sb = (fl & F_SB1) ? 1 : ((fl & F_SB2) ? 2 : 0);
            int sa = (fl & F_SA1) ? 1 : ((fl & F_SA2) ? 2 : 0);
            float wB = (fl & F_HASB) ? bw : w0;
            float wA = sa ? s_res[L * 5 + 4] : w0;
            float w1 = (sb == 1) ? wB : ((sa == 1) ? wA : w0);
            float w2 = (sb == 2) ? wB : ((sa == 2) ? wA : w0);
            bool pick1 = eps_val(w1, wh1, lwp) <= eps_val(w2, wh2, lwp);
            dres = pick1 ? (a2 + 0.5f * w1) : (b2 + 0.5f * w2);
            wres = pick1 ? w1 : w2;
        }
        out[i * 4 + a]     = dres;
        out[i * 4 + 2 + a] = wres;
    }
}

extern "C" void kernel_launch(void* const* d_in, const int* in_sizes, int n_in,
                              void* d_out, int out_size) {
    // metadata order: img, pred, target, crop_shapes, proposal_list, cases, ...
    const float* pred   = (const float*)d_in[1];
    const float* target = (const float*)d_in[2];
    const float* crop   = (const float*)d_in[3];
    const float* prop   = (const float*)d_in[4];
    const int*   cases  = (const int*)d_in[5];
    float* out = (float*)d_out;

    k_fused<<<TOTAL / BLOCK, BLOCK>>>(pred, target, crop, prop, cases, out);
}

// round 10
// speedup vs baseline: 1.0809x; 1.0809x over previous
#include <cuda_runtime.h>
#include <cuda_bf16.h>

// N=131072 rows, output (N,4) f32. JAX bisection bbox relabel, BETA=1.
// R10: R9's structure (one thread per ROW, coalesced float4/int4 loads, both
// axes per thread) with R7's EXACT arithmetic (accurate expf / IEEE divide /
// accurate logf for everything feeding a discrete decision). R9 failed because
// __expf/__fdividef perturbed branch-classification inequalities -> O(1) flips.
// __expf survives only inside bis_g's bounded-derivative middle band.

#define NROWS 131072
#define BLOCK 256
#define MT (2 * BLOCK)                // max tasks per block
#define BISECT_ITERS 34
#define E_F 2.718281828459045f
#define INV_E_F 0.36787944117144233f
#define SMALL_TH 5.656854249492380f   // 4*sqrt(2)

// flag bits
#define F_ISC    1
#define F_RLL    2     // r/l: left mode
#define F_HASB   4
#define F_SMALL  8
#define F_SB1    16    // C: B side is side1
#define F_SB2    32
#define F_SA1    64    // C: A side is side1
#define F_SA2    128

__device__ __forceinline__ float smooth_l1(float x) {
    float d = fabsf(x);
    return d < 1.0f ? 0.5f * d * d : d - 0.5f;
}
__device__ __forceinline__ float eps_val(float w, float wh, float lwp) {
    return smooth_l1((w - wh) * 0.5f) + smooth_l1(logf(fmaxf(w, 1e-12f)) - lwp);
}

// Sign-carrying eval of eps_prime * max(w,1e-12) without log (clip saturates
// outside [wpc/e, e*wpc]; inside, sign(t+log(mh/wpc)) == sign(mh*e^t - wpc):
// one MUFU.EX2, derivative bounded below -> no amplification). sigma: flip at m<0.
__device__ __forceinline__ float bis_g(float m, float wh, float wpc,
                                       float hi, float lo, bool sigma) {
    float mh = fmaxf(m, 1e-12f);
    float cA = fminf(fmaxf((m - wh) * 0.5f, -1.0f), 1.0f);
    float t  = 0.5f * cA * mh;
    float g;
    if (mh >= hi)      g = t + 1.0f;
    else if (mh <= lo) g = t - 1.0f;
    else               g = fmaf(mh, __expf(t), -wpc);
    if (sigma && m < 0.0f) g = -g;
    return g;
}

struct Slot { float u, v, u0, v0, wh, wpc, hi, lo; bool sig; };

__device__ __forceinline__ void slot_init(Slot& s, float u0, float v0,
                                          float wh, float wpc, bool sig) {
    s.u = s.u0 = u0; s.v = s.v0 = v0; s.wh = wh; s.wpc = wpc;
    s.hi = E_F * wpc; s.lo = INV_E_F * wpc; s.sig = sig;
}
__device__ __forceinline__ void slot_step(Slot& s) {
    float m = (s.u + s.v) * 0.5f;
    bool c = bis_g(m, s.wh, s.wpc, s.hi, s.lo, s.sig) >= 0.0f;
    s.v = c ? m : s.v;
    s.u = c ? s.u : m;
}
__device__ __forceinline__ float slot_result(const Slot& s) {
    float m  = (s.u + s.v) * 0.5f;
    float fu = bis_g(s.u0, s.wh, s.wpc, s.hi, s.lo, s.sig);
    float fv = bis_g(s.v0, s.wh, s.wpc, s.hi, s.lo, s.sig);
    return (fu >= 0.0f) ? s.u0 : ((fv <= 0.0f) ? s.v0 : m);
}

// branchB slot k of {c2, c3, c4|c5, c6}: shared (wp, wh, w0).
__device__ __forceinline__ void initB_k(Slot& s, int k, float wp, float wh,
                                        float w0) {
    float wpc = fmaxf(wp, 1e-12f);
    float base = fmaxf(w0, fmaxf(wh - 2.0f, E_F * wp));
    float disc = sqrtf(fmaxf(1.0f - 32.0f / fmaxf(wh * wh, 1e-12f), 0.0f));
    float ebwp = E_F * wp;
    bool smallB = (wh <= SMALL_TH);
    float u, v; bool sig;
    if (k == 0)      { u = fmaxf(w0, wp);     v = fminf(ebwp, wh); sig = false; }  // c2
    else if (k == 1) { u = fmaxf(base, 2.0f); v = wh;              sig = false; }  // c3
    else if (k == 2) {
        if (smallB) { u = base; v = fminf(E_F, wh); }                              // c4
        else        { u = base; v = fminf(fminf(ebwp, wh), wh * 0.25f * (1.0f + disc)); } // c5
        sig = true;
    } else {
        u = fmaxf(base, wh * 0.25f * (1.0f - disc));                               // c6
        v = fminf(ebwp, wh);
        sig = true;
    }
    slot_init(s, u, v, wh, wpc, sig);
}

__global__ void __launch_bounds__(BLOCK) k_fused(
        const float* __restrict__ pred,
        const float* __restrict__ target,
        const float* __restrict__ crop,
        const float* __restrict__ prop,
        const int*   __restrict__ cases,
        float*       __restrict__ out) {
    __shared__ int   s_cnt, s_nslots;
    __shared__ int   s_flags[MT];
    __shared__ int   s_task[MT];                 // (row<<1)|axis
    __shared__ float s_wp[MT], s_whB[MT], s_whA[MT], s_w0[MT];
    __shared__ float s_p1[MT], s_p2[MT];         // a1,b1 (r/l) or a2,b2 (C)
    __shared__ float s_wh1[MT], s_wh2[MT];       // C only
    __shared__ short s_desc[MT * 5];             // (local<<3)|k  (k=0..3 B, 4=A)
    __shared__ float s_res[MT * 5];

    int tid = threadIdx.x;
    if (tid == 0) { s_cnt = 0; s_nslots = 0; }
    __syncthreads();

    // ---------------- phase 1: per-row classify + trivial resolve ---------
    int i = blockIdx.x * BLOCK + tid;
    const float4 pr = ((const float4*)pred)[i];
    const float4 tg = ((const float4*)target)[i];
    const float4 pp = ((const float4*)prop)[i];
    const float4 cr = ((const float4*)crop)[i];
    const int4   cs = ((const int4*)cases)[i];

#pragma unroll
    for (int a = 0; a < 2; a++) {
        float pd    = a ? pr.y : pr.x;
        float plog  = a ? pr.w : pr.z;
        float td    = a ? tg.y : tg.x;
        float tlog  = a ? tg.w : tg.z;
        float p_d   = a ? pp.y : pp.x;
        float p_o   = a ? pp.w : pp.z;
        float cropa = a ? cr.y : cr.x;
        int   lt    = a ? cs.z : cs.x;
        int   rb    = a ? cs.w : cs.y;
        int type = (lt ? 2 : 0) | (rb ? 1 : 0);   // 0=none 1=r 2=l 3=both

        if (type == 0) {
            out[i * 4 + a]     = td;
            out[i * 4 + 2 + a] = expf(tlog);
            continue;
        }
        float to = expf(tlog);
        float ca = 0.5f * (p_d + p_o);
        float da = p_o - p_d;

        if (type != 3) {
            float po = expf(plog);
            float a1, b1, wh;
            if (type == 1) { a1 = td - 0.5f * to; b1 = (cropa - ca) / da; wh = 2.0f * (pd - a1); }
            else           { a1 = -ca / da;       b1 = td + 0.5f * to;   wh = 2.0f * (b1 - pd); }
            float w0 = b1 - a1;
            bool bA = fmaxf(w0, wh) < po;
            bool bB = fmaxf(w0, po) < wh;
            if (!bA && !bB) {
                float d = (type == 1) ? (a1 + 0.5f * w0) : (b1 - 0.5f * w0);
                out[i * 4 + a]     = d;
                out[i * 4 + 2 + a] = w0;
            } else {
                int L = atomicAdd(&s_cnt, 1);
                int fl = (type == 2 ? F_RLL : 0);
                s_task[L] = (i << 1) | a;
                s_wp[L] = po; s_w0[L] = w0;
                s_p1[L] = a1; s_p2[L] = b1;
                int ns, base;
                if (bA) {
                    s_whA[L] = wh;
                    ns = 1;
                    base = atomicAdd(&s_nslots, ns);
                    s_desc[base] = (short)((L << 3) | 4);
                } else {
                    fl |= F_HASB;
                    bool sm = (wh <= SMALL_TH);
                    if (sm) fl |= F_SMALL;
                    s_whB[L] = wh;
                    ns = sm ? 3 : 4;
                    base = atomicAdd(&s_nslots, ns);
                    for (int k = 0; k < ns; k++)
                        s_desc[base + k] = (short)((L << 3) | k);
                }
                s_flags[L] = fl;
            }
        } else {
            float a2 = -ca / da;
            float b2 = (cropa - ca) / da;
            float wh1 = 2.0f * (pd - a2);
            float wh2 = 2.0f * (b2 - pd);
            if (pd >= fmaxf(wh1, wh2)) {          // trivial (wp = dp = pd)
                out[i * 4 + a]     = pd;
                out[i * 4 + 2 + a] = pd;
            } else {
                float w0 = b2 - a2;
                bool A1 = fmaxf(w0, wh1) < pd, B1 = fmaxf(w0, pd) < wh1;
                bool A2 = fmaxf(w0, wh2) < pd, B2 = fmaxf(w0, pd) < wh2;
                if (!(A1 | B1 | A2 | B2)) {       // both sides -> w0
                    float lwp = logf(fmaxf(pd, 1e-12f));
                    bool pick1 = eps_val(w0, wh1, lwp) <= eps_val(w0, wh2, lwp);
                    float d = pick1 ? (a2 + 0.5f * w0) : (b2 + 0.5f * w0);
                    out[i * 4 + a]     = d;
                    out[i * 4 + 2 + a] = w0;
                } else {
                    int L = atomicAdd(&s_cnt, 1);
                    int fl = F_ISC;
                    int sb = B1 ? 1 : (B2 ? 2 : 0);   // at most one B side
                    int sa = A1 ? 1 : (A2 ? 2 : 0);
                    if (sb == 1) fl |= F_SB1; else if (sb == 2) fl |= F_SB2;
                    if (sa == 1) fl |= F_SA1; else if (sa == 2) fl |= F_SA2;
                    float whB = (sb == 1) ? wh1 : wh2;
                    float whA = (sa == 1) ? wh1 : wh2;
                    s_task[L] = (i << 1) | a;
                    s_wp[L] = pd; s_w0[L] = w0;
                    s_p1[L] = a2; s_p2[L] = b2;
                    s_wh1[L] = wh1; s_wh2[L] = wh2;
                    s_whA[L] = whA; s_whB[L] = whB;
                    int nb = 0;
                    bool sm = (whB <= SMALL_TH);
                    if (sb) { fl |= F_HASB; if (sm) fl |= F_SMALL; nb = sm ? 3 : 4; }
                    int ns = nb + (sa ? 1 : 0);
                    int base = atomicAdd(&s_nslots, ns);
                    for (int k = 0; k < nb; k++)
                        s_desc[base + k] = (short)((L << 3) | k);
                    if (sa) s_desc[base + nb] = (short)((L << 3) | 4);
                    s_flags[L] = fl;
                }
            }
        }
    }
    __syncthreads();

    // ---------------- phase 2: slot-parallel bisections -------------------
    int nslots = s_nslots;
    for (int sidx = tid; sidx < nslots; sidx += BLOCK) {
        int d = s_desc[sidx];
        int L = d >> 3, k = d & 7;
        float wp = s_wp[L], w0 = s_w0[L];
        Slot sl;
        if (k == 4) {
            float wh = s_whA[L];
            slot_init(sl, fmaxf(w0, wh), wp, wh, fmaxf(wp, 1e-12f), false);
        } else {
            initB_k(sl, k, wp, s_whB[L], w0);
        }
#pragma unroll 1
        for (int it = 0; it < BISECT_ITERS; it++) slot_step(sl);
        s_res[L * 5 + k] = slot_result(sl);
    }
    __syncthreads();

    // ---------------- phase 3: finalize -----------------------------------
    int cnt = s_cnt;
    for (int L = tid; L < cnt; L += BLOCK) {
        int fl = s_flags[L];
        int tg2 = s_task[L];
        int ri = tg2 >> 1, a = tg2 & 1;
        float wp = s_wp[L], w0 = s_w0[L];
        float lwp = logf(fmaxf(wp, 1e-12f));

        float bw = w0;
        if (fl & F_HASB) {
            float whB = s_whB[L];
            bool sm = (fl & F_SMALL);
            float bv = eps_val(w0, whB, lwp);
            float e1 = eps_val(whB, whB, lwp);
            if (e1 < bv) { bv = e1; bw = whB; }
            float e2 = eps_val(s_res[L * 5 + 0], whB, lwp);
            if (e2 < bv) { bv = e2; bw = s_res[L * 5 + 0]; }
            float e3 = eps_val(s_res[L * 5 + 1], whB, lwp);
            if (e3 < bv) { bv = e3; bw = s_res[L * 5 + 1]; }
            float e4 = eps_val(s_res[L * 5 + 2], whB, lwp);
            if (e4 < bv) { bv = e4; bw = s_res[L * 5 + 2]; }
            if (!sm) {
                float e5 = eps_val(s_res[L * 5 + 3], whB, lwp);
                if (e5 < bv) { bv = e5; bw = s_res[L * 5 + 3]; }
            }
        }

        float dres, wres;
        if (!(fl & F_ISC)) {
            wres = (fl & F_HASB) ? bw : s_res[L * 5 + 4];
            float a1 = s_p1[L], b1 = s_p2[L];
            dres = (fl & F_RLL) ? (b1 - 0.5f * wres) : (a1 + 0.5f * wres);
        } else {
            float a2 = s_p1[L], b2 = s_p2[L];
            float wh1 = s_wh1[L], wh2 = s_wh2[L];
            int sb = (fl & F_SB1) ? 1 : ((fl & F_SB2) ? 2 : 0);
            int sa = (fl & F_SA1) ? 1 : ((fl & F_SA2) ? 2 : 0);
            float wB = (fl & F_HASB) ? bw : w0;
            float wA = sa ? s_res[L * 5 + 4] : w0;
            float w1 = (sb == 1) ? wB : ((sa == 1) ? wA : w0);
            float w2 = (sb == 2) ? wB : ((sa == 2) ? wA : w0);
            bool pick1 = eps_val(w1, wh1, lwp) <= eps_val(w2, wh2, lwp);
            dres = pick1 ? (a2 + 0.5f * w1) : (b2 + 0.5f * w2);
            wres = pick1 ? w1 : w2;
        }
        out[ri * 4 + a]     = dres;
        out[ri * 4 + 2 + a] = wres;
    }
}

extern "C" void kernel_launch(void* const* d_in, const int* in_sizes, int n_in,
                              void* d_out, int out_size) {
    // metadata order: img, pred, target, crop_shapes, proposal_list, cases, ...
    const float* pred   = (const float*)d_in[1];
    const float* target = (const float*)d_in[2];
    const float* crop   = (const float*)d_in[3];
    const float* prop   = (const float*)d_in[4];
    const int*   cases  = (const int*)d_in[5];
    float* out = (float*)d_out;

    k_fused<<<NROWS / BLOCK, BLOCK>>>(pred, target, crop, prop, cases, out);
}

// round 11
// speedup vs baseline: 1.1745x; 1.0865x over previous
#include <cuda_runtime.h>
#include <cuda_bf16.h>

// N=131072 rows, output (N,4) f32. JAX bisection bbox relabel, BETA=1.
// R11: R7 structure (per-(row,axis) threads, 1024 blocks, fused 3-phase) with
// BRANCHLESS classify: the expensive ops of the old divergent branch union
// (2x accurate expf, 2x IEEE divide) are hoisted and computed unconditionally;
// r/l/both geometry derived by selects using expressions identical to the
// reference per type. Decision arithmetic unchanged -> bitwise-same selections.

#define NROWS 131072
#define TOTAL (2 * NROWS)
#define BLOCK 256
#define MT BLOCK                      // max tasks per block (1 per thread)
#define BISECT_ITERS 34
#define E_F 2.718281828459045f
#define INV_E_F 0.36787944117144233f
#define SMALL_TH 5.656854249492380f   // 4*sqrt(2)

// flag bits
#define F_ISC    1
#define F_RLL    2     // r/l: left mode
#define F_HASB   4
#define F_SMALL  8
#define F_SB1    16    // C: B side is side1
#define F_SB2    32
#define F_SA1    64    // C: A side is side1
#define F_SA2    128

__device__ __forceinline__ float smooth_l1(float x) {
    float d = fabsf(x);
    return d < 1.0f ? 0.5f * d * d : d - 0.5f;
}
__device__ __forceinline__ float eps_val(float w, float wh, float lwp) {
    return smooth_l1((w - wh) * 0.5f) + smooth_l1(logf(fmaxf(w, 1e-12f)) - lwp);
}

// Sign-carrying eval of eps_prime * max(w,1e-12) without log (clip saturates
// outside [wpc/e, e*wpc]; inside, sign(t+log(mh/wpc)) == sign(mh*e^t - wpc):
// one MUFU.EX2, derivative bounded below -> no amplification). sigma: flip at m<0.
__device__ __forceinline__ float bis_g(float m, float wh, float wpc,
                                       float hi, float lo, bool sigma) {
    float mh = fmaxf(m, 1e-12f);
    float cA = fminf(fmaxf((m - wh) * 0.5f, -1.0f), 1.0f);
    float t  = 0.5f * cA * mh;
    float g;
    if (mh >= hi)      g = t + 1.0f;
    else if (mh <= lo) g = t - 1.0f;
    else               g = fmaf(mh, __expf(t), -wpc);
    if (sigma && m < 0.0f) g = -g;
    return g;
}

struct Slot { float u, v, u0, v0, wh, wpc, hi, lo; bool sig; };

__device__ __forceinline__ void slot_init(Slot& s, float u0, float v0,
                                          float wh, float wpc, bool sig) {
    s.u = s.u0 = u0; s.v = s.v0 = v0; s.wh = wh; s.wpc = wpc;
    s.hi = E_F * wpc; s.lo = INV_E_F * wpc; s.sig = sig;
}
__device__ __forceinline__ void slot_step(Slot& s) {
    float m = (s.u + s.v) * 0.5f;
    bool c = bis_g(m, s.wh, s.wpc, s.hi, s.lo, s.sig) >= 0.0f;
    s.v = c ? m : s.v;
    s.u = c ? s.u : m;
}
__device__ __forceinline__ float slot_result(const Slot& s) {
    float m  = (s.u + s.v) * 0.5f;
    float fu = bis_g(s.u0, s.wh, s.wpc, s.hi, s.lo, s.sig);
    float fv = bis_g(s.v0, s.wh, s.wpc, s.hi, s.lo, s.sig);
    return (fu >= 0.0f) ? s.u0 : ((fv <= 0.0f) ? s.v0 : m);
}

// branchB slot k of {c2, c3, c4|c5, c6}: shared (wp, wh, w0).
__device__ __forceinline__ void initB_k(Slot& s, int k, float wp, float wh,
                                        float w0) {
    float wpc = fmaxf(wp, 1e-12f);
    float base = fmaxf(w0, fmaxf(wh - 2.0f, E_F * wp));
    float disc = sqrtf(fmaxf(1.0f - 32.0f / fmaxf(wh * wh, 1e-12f), 0.0f));
    float ebwp = E_F * wp;
    bool smallB = (wh <= SMALL_TH);
    float u, v; bool sig;
    if (k == 0)      { u = fmaxf(w0, wp);     v = fminf(ebwp, wh); sig = false; }  // c2
    else if (k == 1) { u = fmaxf(base, 2.0f); v = wh;              sig = false; }  // c3
    else if (k == 2) {
        if (smallB) { u = base; v = fminf(E_F, wh); }                              // c4
        else        { u = base; v = fminf(fminf(ebwp, wh), wh * 0.25f * (1.0f + disc)); } // c5
        sig = true;
    } else {
        u = fmaxf(base, wh * 0.25f * (1.0f - disc));                               // c6
        v = fminf(ebwp, wh);
        sig = true;
    }
    slot_init(s, u, v, wh, wpc, sig);
}

__global__ void __launch_bounds__(BLOCK) k_fused(
        const float* __restrict__ pred,
        const float* __restrict__ target,
        const float* __restrict__ crop,
        const float* __restrict__ prop,
        const int*   __restrict__ cases,
        float*       __restrict__ out) {
    __shared__ int   s_cnt, s_nslots;
    __shared__ int   s_flags[MT];
    __shared__ int   s_task[MT];                 // (row<<1)|axis
    __shared__ float s_wp[MT], s_whB[MT], s_whA[MT], s_w0[MT];
    __shared__ float s_p1[MT], s_p2[MT];         // a1,b1 (r/l) or a2,b2 (C)
    __shared__ float s_wh1[MT], s_wh2[MT];       // C only
    __shared__ short s_desc[MT * 5];             // (local<<3)|k  (k=0..3 B, 4=A)
    __shared__ float s_res[MT * 5];

    int tid = threadIdx.x;
    if (tid == 0) { s_cnt = 0; s_nslots = 0; }
    __syncthreads();

    // ---------------- phase 1: branchless classify ------------------------
    int t = blockIdx.x * BLOCK + tid;
    int i = t >> 1, a = t & 1;
    const float4 pr = ((const float4*)pred)[i];
    const float4 tg = ((const float4*)target)[i];
    const float4 pp = ((const float4*)prop)[i];
    const float4 cr = ((const float4*)crop)[i];
    const int4   cs = ((const int4*)cases)[i];

    float pd    = a ? pr.y : pr.x;
    float plog  = a ? pr.w : pr.z;
    float td    = a ? tg.y : tg.x;
    float tlog  = a ? tg.w : tg.z;
    float p_d   = a ? pp.y : pp.x;
    float p_o   = a ? pp.w : pp.z;
    float cropa = a ? cr.y : cr.x;
    int   lt    = a ? cs.z : cs.x;
    int   rb    = a ? cs.w : cs.y;
    int type = (lt ? 2 : 0) | (rb ? 1 : 0);   // 0=none 1=r 2=l 3=both

    // hoisted heavy ops (accurate; identical expressions to reference)
    float to = expf(tlog);
    float po = expf(plog);
    float ca = 0.5f * (p_d + p_o);
    float da = p_o - p_d;
    float q1 = -ca / da;               // l: a1, both: a2
    float q2 = (cropa - ca) / da;      // r: b1, both: b2

    // r/l unified geometry (selects, not branches)
    bool isR = (type == 1);
    float a1 = isR ? (td - 0.5f * to) : q1;
    float b1 = isR ? q2 : (td + 0.5f * to);
    float wh = isR ? 2.0f * (pd - a1) : 2.0f * (b1 - pd);
    float w0 = b1 - a1;
    // both geometry
    float wh1 = 2.0f * (pd - q1);
    float wh2 = 2.0f * (q2 - pd);
    float w0b = q2 - q1;

    bool write = true;
    float dres = td, wres = to;        // type 0 defaults

    if (type == 1 || type == 2) {
        bool bA = fmaxf(w0, wh) < po;
        bool bB = fmaxf(w0, po) < wh;
        if (!bA && !bB) {
            dres = isR ? (a1 + 0.5f * w0) : (b1 - 0.5f * w0);
            wres = w0;
        } else {
            write = false;
            int L = atomicAdd(&s_cnt, 1);
            int fl = (type == 2 ? F_RLL : 0);
            s_task[L] = t;
            s_wp[L] = po; s_w0[L] = w0;
            s_p1[L] = a1; s_p2[L] = b1;
            int ns, base;
            if (bA) {
                s_whA[L] = wh;
                ns = 1;
                base = atomicAdd(&s_nslots, ns);
                s_desc[base] = (short)((L << 3) | 4);
            } else {
                fl |= F_HASB;
                bool sm = (wh <= SMALL_TH);
                if (sm) fl |= F_SMALL;
                s_whB[L] = wh;
                ns = sm ? 3 : 4;
                base = atomicAdd(&s_nslots, ns);
                for (int k = 0; k < ns; k++)
                    s_desc[base + k] = (short)((L << 3) | k);
            }
            s_flags[L] = fl;
        }
    } else if (type == 3) {
        if (pd >= fmaxf(wh1, wh2)) {           // trivial (wp = dp = pd)
            dres = pd; wres = pd;
        } else {
            bool A1 = fmaxf(w0b, wh1) < pd, B1 = fmaxf(w0b, pd) < wh1;
            bool A2 = fmaxf(w0b, wh2) < pd, B2 = fmaxf(w0b, pd) < wh2;
            if (!(A1 | B1 | A2 | B2)) {        // both sides -> w0b
                float lwp = logf(fmaxf(pd, 1e-12f));
                bool pick1 = eps_val(w0b, wh1, lwp) <= eps_val(w0b, wh2, lwp);
                dres = pick1 ? (q1 + 0.5f * w0b) : (q2 + 0.5f * w0b);
                wres = w0b;
            } else {
                write = false;
                int L = atomicAdd(&s_cnt, 1);
                int fl = F_ISC;
                int sb = B1 ? 1 : (B2 ? 2 : 0);    // at most one B side
                int sa = A1 ? 1 : (A2 ? 2 : 0);
                if (sb == 1) fl |= F_SB1; else if (sb == 2) fl |= F_SB2;
                if (sa == 1) fl |= F_SA1; else if (sa == 2) fl |= F_SA2;
                float whB = (sb == 1) ? wh1 : wh2;
                float whA = (sa == 1) ? wh1 : wh2;
                s_task[L] = t;
                s_wp[L] = pd; s_w0[L] = w0b;
                s_p1[L] = q1; s_p2[L] = q2;
                s_wh1[L] = wh1; s_wh2[L] = wh2;
                s_whA[L] = whA; s_whB[L] = whB;
                int nb = 0;
                bool sm = (whB <= SMALL_TH);
                if (sb) { fl |= F_HASB; if (sm) fl |= F_SMALL; nb = sm ? 3 : 4; }
                int ns = nb + (sa ? 1 : 0);
                int base = atomicAdd(&s_nslots, ns);
                for (int k = 0; k < nb; k++)
                    s_desc[base + k] = (short)((L << 3) | k);
                if (sa) s_desc[base + nb] = (short)((L << 3) | 4);
                s_flags[L] = fl;
            }
        }
    }
    if (write) {
        out[i * 4 + a]     = dres;
        out[i * 4 + 2 + a] = wres;
    }
    __syncthreads();

    // ---------------- phase 2: slot-parallel bisections -------------------
    int nslots = s_nslots;
    for (int sidx = tid; sidx < nslots; sidx += BLOCK) {
        int d = s_desc[sidx];
        int L = d >> 3, k = d & 7;
        float wp = s_wp[L], w0s = s_w0[L];
        Slot sl;
        if (k == 4) {
            float whS = s_whA[L];
            slot_init(sl, fmaxf(w0s, whS), wp, whS, fmaxf(wp, 1e-12f), false);
        } else {
            initB_k(sl, k, wp, s_whB[L], w0s);
        }
#pragma unroll 1
        for (int it = 0; it < BISECT_ITERS; it++) slot_step(sl);
        s_res[L * 5 + k] = slot_result(sl);
    }
    __syncthreads();

    // ---------------- phase 3: finalize -----------------------------------
    int cnt = s_cnt;
    for (int L = tid; L < cnt; L += BLOCK) {
        int fl = s_flags[L];
        int tg2 = s_task[L];
        int ri = tg2 >> 1, ax = tg2 & 1;
        float wp = s_wp[L], w0s = s_w0[L];
        float lwp = logf(fmaxf(wp, 1e-12f));

        float bw = w0s;
        if (fl & F_HASB) {
            float whB = s_whB[L];
            bool sm = (fl & F_SMALL);
            float bv = eps_val(w0s, whB, lwp);
            float e1 = eps_val(whB, whB, lwp);
            if (e1 < bv) { bv = e1; bw = whB; }
            float e2 = eps_val(s_res[L * 5 + 0], whB, lwp);
            if (e2 < bv) { bv = e2; bw = s_res[L * 5 + 0]; }
            float e3 = eps_val(s_res[L * 5 + 1], whB, lwp);
            if (e3 < bv) { bv = e3; bw = s_res[L * 5 + 1]; }
            float e4 = eps_val(s_res[L * 5 + 2], whB, lwp);
            if (e4 < bv) { bv = e4; bw = s_res[L * 5 + 2]; }
            if (!sm) {
                float e5 = eps_val(s_res[L * 5 + 3], whB, lwp);
                if (e5 < bv) { bv = e5; bw = s_res[L * 5 + 3]; }
            }
        }

        float dr, wr;
        if (!(fl & F_ISC)) {
            wr = (fl & F_HASB) ? bw : s_res[L * 5 + 4];
            float aa1 = s_p1[L], bb1 = s_p2[L];
            dr = (fl & F_RLL) ? (bb1 - 0.5f * wr) : (aa1 + 0.5f * wr);
        } else {
            float a2 = s_p1[L], b2 = s_p2[L];
            float w1h = s_wh1[L], w2h = s_wh2[L];
            int sb = (fl & F_SB1) ? 1 : ((fl & F_SB2) ? 2 : 0);
            int sa = (fl & F_SA1) ? 1 : ((fl & F_SA2) ? 2 : 0);
            float wB = (fl & F_HASB) ? bw : w0s;
            float wA = sa ? s_res[L * 5 + 4] : w0s;
            float w1 = (sb == 1) ? wB : ((sa == 1) ? wA : w0s);
            float w2 = (sb == 2) ? wB : ((sa == 2) ? wA : w0s);
            bool pick1 = eps_val(w1, w1h, lwp) <= eps_val(w2, w2h, lwp);
            dr = pick1 ? (a2 + 0.5f * w1) : (b2 + 0.5f * w2);
            wr = pick1 ? w1 : w2;
        }
        out[ri * 4 + ax]     = dr;
        out[ri * 4 + 2 + ax] = wr;
    }
}

extern "C" void kernel_launch(void* const* d_in, const int* in_sizes, int n_in,
                              void* d_out, int out_size) {
    // metadata order: img, pred, target, crop_shapes, proposal_list, cases, ...
    const float* pred   = (const float*)d_in[1];
    const float* target = (const float*)d_in[2];
    const float* crop   = (const float*)d_in[3];
    const float* prop   = (const float*)d_in[4];
    const int*   cases  = (const int*)d_in[5];
    float* out = (float*)d_out;

    k_fused<<<TOTAL / BLOCK, BLOCK>>>(pred, target, crop, prop, cases, out);
}

// round 12
// speedup vs baseline: 1.1875x; 1.0111x over previous
#include <cuda_runtime.h>
#include <cuda_bf16.h>

// N=131072 rows, output (N,4) f32. JAX bisection bbox relabel, BETA=1.
// R12: R11 branchless-classify fused kernel with (a) BISECT_ITERS 34->28
// (residual < existing __expf-band noise), (b) candidate eps_val moved into
// phase 2 (parallel across slot threads; finalize = compares only),
// (c) BLOCK 128 for lower per-block slot variance and barrier skew.

#define NROWS 131072
#define TOTAL (2 * NROWS)
#define BLOCK 128
#define MT BLOCK                      // max tasks per block (1 per thread)
#define BISECT_ITERS 28
#define E_F 2.718281828459045f
#define INV_E_F 0.36787944117144233f
#define SMALL_TH 5.656854249492380f   // 4*sqrt(2)

// flag bits
#define F_ISC    1
#define F_RLL    2     // r/l: left mode
#define F_HASB   4
#define F_SMALL  8
#define F_SB1    16    // C: B side is side1
#define F_SB2    32
#define F_SA1    64    // C: A side is side1
#define F_SA2    128

__device__ __forceinline__ float smooth_l1(float x) {
    float d = fabsf(x);
    return d < 1.0f ? 0.5f * d * d : d - 0.5f;
}
__device__ __forceinline__ float eps_val(float w, float wh, float lwp) {
    return smooth_l1((w - wh) * 0.5f) + smooth_l1(logf(fmaxf(w, 1e-12f)) - lwp);
}

// Sign-carrying eval of eps_prime * max(w,1e-12) without log (clip saturates
// outside [wpc/e, e*wpc]; inside, sign(t+log(mh/wpc)) == sign(mh*e^t - wpc):
// one MUFU.EX2, derivative bounded below -> no amplification). sigma: flip at m<0.
__device__ __forceinline__ float bis_g(float m, float wh, float wpc,
                                       float hi, float lo, bool sigma) {
    float mh = fmaxf(m, 1e-12f);
    float cA = fminf(fmaxf((m - wh) * 0.5f, -1.0f), 1.0f);
    float t  = 0.5f * cA * mh;
    float g;
    if (mh >= hi)      g = t + 1.0f;
    else if (mh <= lo) g = t - 1.0f;
    else               g = fmaf(mh, __expf(t), -wpc);
    if (sigma && m < 0.0f) g = -g;
    return g;
}

struct Slot { float u, v, u0, v0, wh, wpc, hi, lo; bool sig; };

__device__ __forceinline__ void slot_init(Slot& s, float u0, float v0,
                                          float wh, float wpc, bool sig) {
    s.u = s.u0 = u0; s.v = s.v0 = v0; s.wh = wh; s.wpc = wpc;
    s.hi = E_F * wpc; s.lo = INV_E_F * wpc; s.sig = sig;
}
__device__ __forceinline__ void slot_step(Slot& s) {
    float m = (s.u + s.v) * 0.5f;
    bool c = bis_g(m, s.wh, s.wpc, s.hi, s.lo, s.sig) >= 0.0f;
    s.v = c ? m : s.v;
    s.u = c ? s.u : m;
}
__device__ __forceinline__ float slot_result(const Slot& s) {
    float m  = (s.u + s.v) * 0.5f;
    float fu = bis_g(s.u0, s.wh, s.wpc, s.hi, s.lo, s.sig);
    float fv = bis_g(s.v0, s.wh, s.wpc, s.hi, s.lo, s.sig);
    return (fu >= 0.0f) ? s.u0 : ((fv <= 0.0f) ? s.v0 : m);
}

// branchB slot k of {c2, c3, c4|c5, c6}: shared (wp, wh, w0).
__device__ __forceinline__ void initB_k(Slot& s, int k, float wp, float wh,
                                        float w0) {
    float wpc = fmaxf(wp, 1e-12f);
    float base = fmaxf(w0, fmaxf(wh - 2.0f, E_F * wp));
    float disc = sqrtf(fmaxf(1.0f - 32.0f / fmaxf(wh * wh, 1e-12f), 0.0f));
    float ebwp = E_F * wp;
    bool smallB = (wh <= SMALL_TH);
    float u, v; bool sig;
    if (k == 0)      { u = fmaxf(w0, wp);     v = fminf(ebwp, wh); sig = false; }  // c2
    else if (k == 1) { u = fmaxf(base, 2.0f); v = wh;              sig = false; }  // c3
    else if (k == 2) {
        if (smallB) { u = base; v = fminf(E_F, wh); }                              // c4
        else        { u = base; v = fminf(fminf(ebwp, wh), wh * 0.25f * (1.0f + disc)); } // c5
        sig = true;
    } else {
        u = fmaxf(base, wh * 0.25f * (1.0f - disc));                               // c6
        v = fminf(ebwp, wh);
        sig = true;
    }
    slot_init(s, u, v, wh, wpc, sig);
}

__global__ void __launch_bounds__(BLOCK) k_fused(
        const float* __restrict__ pred,
        const float* __restrict__ target,
        const float* __restrict__ crop,
        const float* __restrict__ prop,
        const int*   __restrict__ cases,
        float*       __restrict__ out) {
    __shared__ int   s_cnt, s_nslots;
    __shared__ int   s_flags[MT];
    __shared__ int   s_task[MT];                 // (row<<1)|axis
    __shared__ float s_wp[MT], s_whB[MT], s_whA[MT], s_w0[MT];
    __shared__ float s_p1[MT], s_p2[MT];         // a1,b1 (r/l) or a2,b2 (C)
    __shared__ float s_wh1[MT], s_wh2[MT];       // C only
    __shared__ short s_desc[MT * 5];             // (local<<3)|k  (k=0..3 B, 4=A)
    __shared__ float s_res[MT * 5];
    __shared__ float s_eps[MT * 4];              // eps of B-slot results
    __shared__ float s_epsw0[MT], s_epswh[MT];   // eps(w0), eps(whB)

    int tid = threadIdx.x;
    if (tid == 0) { s_cnt = 0; s_nslots = 0; }
    __syncthreads();

    // ---------------- phase 1: branchless classify ------------------------
    int t = blockIdx.x * BLOCK + tid;
    int i = t >> 1, a = t & 1;
    const float4 pr = ((const float4*)pred)[i];
    const float4 tg = ((const float4*)target)[i];
    const float4 pp = ((const float4*)prop)[i];
    const float4 cr = ((const float4*)crop)[i];
    const int4   cs = ((const int4*)cases)[i];

    float pd    = a ? pr.y : pr.x;
    float plog  = a ? pr.w : pr.z;
    float td    = a ? tg.y : tg.x;
    float tlog  = a ? tg.w : tg.z;
    float p_d   = a ? pp.y : pp.x;
    float p_o   = a ? pp.w : pp.z;
    float cropa = a ? cr.y : cr.x;
    int   lt    = a ? cs.z : cs.x;
    int   rb    = a ? cs.w : cs.y;
    int type = (lt ? 2 : 0) | (rb ? 1 : 0);   // 0=none 1=r 2=l 3=both

    // hoisted heavy ops (accurate; identical expressions to reference)
    float to = expf(tlog);
    float po = expf(plog);
    float ca = 0.5f * (p_d + p_o);
    float da = p_o - p_d;
    float q1 = -ca / da;               // l: a1, both: a2
    float q2 = (cropa - ca) / da;      // r: b1, both: b2

    bool isR = (type == 1);
    float a1 = isR ? (td - 0.5f * to) : q1;
    float b1 = isR ? q2 : (td + 0.5f * to);
    float wh = isR ? 2.0f * (pd - a1) : 2.0f * (b1 - pd);
    float w0 = b1 - a1;
    float wh1 = 2.0f * (pd - q1);
    float wh2 = 2.0f * (q2 - pd);
    float w0b = q2 - q1;

    bool write = true;
    float dres = td, wres = to;        // type 0 defaults

    if (type == 1 || type == 2) {
        bool bA = fmaxf(w0, wh) < po;
        bool bB = fmaxf(w0, po) < wh;
        if (!bA && !bB) {
            dres = isR ? (a1 + 0.5f * w0) : (b1 - 0.5f * w0);
            wres = w0;
        } else {
            write = false;
            int L = atomicAdd(&s_cnt, 1);
            int fl = (type == 2 ? F_RLL : 0);
            s_task[L] = t;
            s_wp[L] = po; s_w0[L] = w0;
            s_p1[L] = a1; s_p2[L] = b1;
            int ns, base;
            if (bA) {
                s_whA[L] = wh;
                ns = 1;
                base = atomicAdd(&s_nslots, ns);
                s_desc[base] = (short)((L << 3) | 4);
            } else {
                fl |= F_HASB;
                bool sm = (wh <= SMALL_TH);
                if (sm) fl |= F_SMALL;
                s_whB[L] = wh;
                ns = sm ? 3 : 4;
                base = atomicAdd(&s_nslots, ns);
                for (int k = 0; k < ns; k++)
                    s_desc[base + k] = (short)((L << 3) | k);
            }
            s_flags[L] = fl;
        }
    } else if (type == 3) {
        if (pd >= fmaxf(wh1, wh2)) {           // trivial (wp = dp = pd)
            dres = pd; wres = pd;
        } else {
            bool A1 = fmaxf(w0b, wh1) < pd, B1 = fmaxf(w0b, pd) < wh1;
            bool A2 = fmaxf(w0b, wh2) < pd, B2 = fmaxf(w0b, pd) < wh2;
            if (!(A1 | B1 | A2 | B2)) {        // both sides -> w0b
                float lwp = logf(fmaxf(pd, 1e-12f));
                bool pick1 = eps_val(w0b, wh1, lwp) <= eps_val(w0b, wh2, lwp);
                dres = pick1 ? (q1 + 0.5f * w0b) : (q2 + 0.5f * w0b);
                wres = w0b;
            } else {
                write = false;
                int L = atomicAdd(&s_cnt, 1);
                int fl = F_ISC;
                int sb = B1 ? 1 : (B2 ? 2 : 0);    // at most one B side
                int sa = A1 ? 1 : (A2 ? 2 : 0);
                if (sb == 1) fl |= F_SB1; else if (sb == 2) fl |= F_SB2;
                if (sa == 1) fl |= F_SA1; else if (sa == 2) fl |= F_SA2;
                float whB = (sb == 1) ? wh1 : wh2;
                float whA = (sa == 1) ? wh1 : wh2;
                s_task[L] = t;
                s_wp[L] = pd; s_w0[L] = w0b;
                s_p1[L] = q1; s_p2[L] = q2;
                s_wh1[L] = wh1; s_wh2[L] = wh2;
                s_whA[L] = whA; s_whB[L] = whB;
                int nb = 0;
                bool sm = (whB <= SMALL_TH);
                if (sb) { fl |= F_HASB; if (sm) fl |= F_SMALL; nb = sm ? 3 : 4; }
                int ns = nb + (sa ? 1 : 0);
                int base = atomicAdd(&s_nslots, ns);
                for (int k = 0; k < nb; k++)
                    s_desc[base + k] = (short)((L << 3) | k);
                if (sa) s_desc[base + nb] = (short)((L << 3) | 4);
                s_flags[L] = fl;
            }
        }
    }
    if (write) {
        out[i * 4 + a]     = dres;
        out[i * 4 + 2 + a] = wres;
    }
    __syncthreads();

    // ------- phase 2: slot-parallel bisections + parallel eps evals -------
    int nslots = s_nslots;
    for (int sidx = tid; sidx < nslots; sidx += BLOCK) {
        int d = s_desc[sidx];
        int L = d >> 3, k = d & 7;
        float wp = s_wp[L], w0s = s_w0[L];
        Slot sl;
        if (k == 4) {
            float whS = s_whA[L];
            slot_init(sl, fmaxf(w0s, whS), wp, whS, fmaxf(wp, 1e-12f), false);
        } else {
            initB_k(sl, k, wp, s_whB[L], w0s);
        }
#pragma unroll 1
        for (int it = 0; it < BISECT_ITERS; it++) slot_step(sl);
        float r = slot_result(sl);
        s_res[L * 5 + k] = r;
        if (k != 4) {
            float lwp = logf(fmaxf(wp, 1e-12f));
            float whB = s_whB[L];
            s_eps[L * 4 + k] = eps_val(r, whB, lwp);
            if (k == 0) {
                s_epsw0[L] = eps_val(w0s, whB, lwp);
                s_epswh[L] = eps_val(whB, whB, lwp);
            }
        }
    }
    __syncthreads();

    // ---------------- phase 3: finalize (compares only + C pick1) ---------
    int cnt = s_cnt;
    for (int L = tid; L < cnt; L += BLOCK) {
        int fl = s_flags[L];
        int tg2 = s_task[L];
        int ri = tg2 >> 1, ax = tg2 & 1;
        float w0s = s_w0[L];

        float bw = w0s;
        if (fl & F_HASB) {
            float whB = s_whB[L];
            bool sm = (fl & F_SMALL);
            float bv = s_epsw0[L];
            float e1 = s_epswh[L];
            if (e1 < bv) { bv = e1; bw = whB; }
            float e2 = s_eps[L * 4 + 0];
            if (e2 < bv) { bv = e2; bw = s_res[L * 5 + 0]; }
            float e3 = s_eps[L * 4 + 1];
            if (e3 < bv) { bv = e3; bw = s_res[L * 5 + 1]; }
            float e4 = s_eps[L * 4 + 2];
            if (e4 < bv) { bv = e4; bw = s_res[L * 5 + 2]; }
            if (!sm) {
                float e5 = s_eps[L * 4 + 3];
                if (e5 < bv) { bv = e5; bw = s_res[L * 5 + 3]; }
            }
        }

        float dr, wr;
        if (!(fl & F_ISC)) {
            wr = (fl & F_HASB) ? bw : s_res[L * 5 + 4];
            float aa1 = s_p1[L], bb1 = s_p2[L];
            dr = (fl & F_RLL) ? (bb1 - 0.5f * wr) : (aa1 + 0.5f * wr);
        } else {
            float a2 = s_p1[L], b2 = s_p2[L];
            float w1h = s_wh1[L], w2h = s_wh2[L];
            int sb = (fl & F_SB1) ? 1 : ((fl & F_SB2) ? 2 : 0);
            int sa = (fl & F_SA1) ? 1 : ((fl & F_SA2) ? 2 : 0);
            float wB = (fl & F_HASB) ? bw : w0s;
            float wA = sa ? s_res[L * 5 + 4] : w0s;
            float w1 = (sb == 1) ? wB : ((sa == 1) ? wA : w0s);
            float w2 = (sb == 2) ? wB : ((sa == 2) ? wA : w0s);
            float lwp = logf(fmaxf(s_wp[L], 1e-12f));
            bool pick1 = eps_val(w1, w1h, lwp) <= eps_val(w2, w2h, lwp);
            dr = pick1 ? (a2 + 0.5f * w1) : (b2 + 0.5f * w2);
            wr = pick1 ? w1 : w2;
        }
        out[ri * 4 + ax]     = dr;
        out[ri * 4 + 2 + ax] = wr;
    }
}

extern "C" void kernel_launch(void* const* d_in, const int* in_sizes, int n_in,
                              void* d_out, int out_size) {
    // metadata order: img, pred, target, crop_shapes, proposal_list, cases, ...
    const float* pred   = (const float*)d_in[1];
    const float* target = (const float*)d_in[2];
    const float* crop   = (const float*)d_in[3];
    const float* prop   = (const float*)d_in[4];
    const int*   cases  = (const int*)d_in[5];
    float* out = (float*)d_out;

    k_fused<<<TOTAL / BLOCK, BLOCK>>>(pred, target, crop, prop, cases, out);
}

// round 13
// speedup vs baseline: 1.4443x; 1.2162x over previous
#include <cuda_runtime.h>
#include <cuda_bf16.h>

// N=131072 rows, output (N,4) f32. JAX bisection bbox relabel, BETA=1.
// R13: phase-2 endpoint short-circuit (reference returns u0 if f(u0)>=0, v0 if
// f(v0)<=0, regardless of bisection -> evaluate endpoints FIRST, loop only if
// f(u0)<0<f(v0)), with re-compaction of surviving slots so loop warps are
// dense. Branchless band-select in bis_g (no BSSY/BSYNC in hot loop).
// Both-mode tasks always carry a B-package (wh_max > w0 > pd), so phase 2 is
// the grid-wide dominant cost — this targets it directly.

#define NROWS 131072
#define TOTAL (2 * NROWS)
#define BLOCK 128
#define MT BLOCK
#define MAXS (MT * 5)
#define BISECT_ITERS 28
#define E_F 2.718281828459045f
#define INV_E_F 0.36787944117144233f
#define SMALL_TH 5.656854249492380f   // 4*sqrt(2)

// flag bits
#define F_ISC    1
#define F_RLL    2
#define F_HASB   4
#define F_SMALL  8
#define F_SB1    16
#define F_SB2    32
#define F_SA1    64
#define F_SA2    128

__device__ __forceinline__ float smooth_l1(float x) {
    float d = fabsf(x);
    return d < 1.0f ? 0.5f * d * d : d - 0.5f;
}
__device__ __forceinline__ float eps_val(float w, float wh, float lwp) {
    return smooth_l1((w - wh) * 0.5f) + smooth_l1(logf(fmaxf(w, 1e-12f)) - lwp);
}

// Branchless sign-carrying eval of eps_prime * max(w,1e-12):
// band-saturated outside [wpc/e, e*wpc]; inside sign(mh*e^t - wpc).
// sigma (w*eps'): flip sign when m < 0.
__device__ __forceinline__ float bis_g(float m, float wh, float wpc,
                                       float hi, float lo, bool sigma) {
    float mh = fmaxf(m, 1e-12f);
    float cA = fminf(fmaxf((m - wh) * 0.5f, -1.0f), 1.0f);
    float t  = 0.5f * cA * mh;
    float gmid = fmaf(mh, __expf(t), -wpc);
    float g = (mh >= hi) ? (t + 1.0f) : ((mh <= lo) ? (t - 1.0f) : gmid);
    if (sigma && m < 0.0f) g = -g;
    return g;
}

// slot k: 0..3 = branchB {c2, c3, c4|c5, c6}, 4 = branchA (cA).
__device__ __forceinline__ void init_slot(int k, float wp, float whB, float whA,
                                          float w0, float& u, float& v,
                                          float& wh, float& wpc, bool& sig) {
    wpc = fmaxf(wp, 1e-12f);
    if (k == 4) {
        u = fmaxf(w0, whA); v = wp; wh = whA; sig = false;
        return;
    }
    wh = whB;
    float base = fmaxf(w0, fmaxf(whB - 2.0f, E_F * wp));
    float disc = sqrtf(fmaxf(1.0f - 32.0f / fmaxf(whB * whB, 1e-12f), 0.0f));
    float ebwp = E_F * wp;
    bool smallB = (whB <= SMALL_TH);
    if (k == 0)      { u = fmaxf(w0, wp);     v = fminf(ebwp, whB); sig = false; }
    else if (k == 1) { u = fmaxf(base, 2.0f); v = whB;              sig = false; }
    else if (k == 2) {
        if (smallB) { u = base; v = fminf(E_F, whB); }
        else        { u = base; v = fminf(fminf(ebwp, whB), whB * 0.25f * (1.0f + disc)); }
        sig = true;
    } else {
        u = fmaxf(base, whB * 0.25f * (1.0f - disc));
        v = fminf(ebwp, whB);
        sig = true;
    }
}

__global__ void __launch_bounds__(BLOCK) k_fused(
        const float* __restrict__ pred,
        const float* __restrict__ target,
        const float* __restrict__ crop,
        const float* __restrict__ prop,
        const int*   __restrict__ cases,
        float*       __restrict__ out) {
    __shared__ int   s_cnt, s_nslots, s_cnt2;
    __shared__ int   s_flags[MT];
    __shared__ int   s_task[MT];
    __shared__ float s_wp[MT], s_whB[MT], s_whA[MT], s_w0[MT];
    __shared__ float s_p1[MT], s_p2[MT];
    __shared__ float s_wh1[MT], s_wh2[MT];
    __shared__ short s_desc[MAXS];               // (local<<3)|k
    __shared__ short s_it[MAXS];                 // survivors needing iteration
    __shared__ float s_res[MT * 5];

    int tid = threadIdx.x;
    if (tid == 0) { s_cnt = 0; s_nslots = 0; s_cnt2 = 0; }
    __syncthreads();

    // ---------------- phase 1: branchless classify ------------------------
    int t = blockIdx.x * BLOCK + tid;
    int i = t >> 1, a = t & 1;
    const float4 pr = ((const float4*)pred)[i];
    const float4 tg = ((const float4*)target)[i];
    const float4 pp = ((const float4*)prop)[i];
    const float4 cr = ((const float4*)crop)[i];
    const int4   cs = ((const int4*)cases)[i];

    float pd    = a ? pr.y : pr.x;
    float plog  = a ? pr.w : pr.z;
    float td    = a ? tg.y : tg.x;
    float tlog  = a ? tg.w : tg.z;
    float p_d   = a ? pp.y : pp.x;
    float p_o   = a ? pp.w : pp.z;
    float cropa = a ? cr.y : cr.x;
    int   lt    = a ? cs.z : cs.x;
    int   rb    = a ? cs.w : cs.y;
    int type = (lt ? 2 : 0) | (rb ? 1 : 0);

    float to = expf(tlog);
    float po = expf(plog);
    float ca = 0.5f * (p_d + p_o);
    float da = p_o - p_d;
    float q1 = -ca / da;
    float q2 = (cropa - ca) / da;

    bool isR = (type == 1);
    float a1 = isR ? (td - 0.5f * to) : q1;
    float b1 = isR ? q2 : (td + 0.5f * to);
    float wh = isR ? 2.0f * (pd - a1) : 2.0f * (b1 - pd);
    float w0 = b1 - a1;
    float wh1 = 2.0f * (pd - q1);
    float wh2 = 2.0f * (q2 - pd);
    float w0b = q2 - q1;

    bool write = true;
    float dres = td, wres = to;

    if (type == 1 || type == 2) {
        bool bA = fmaxf(w0, wh) < po;
        bool bB = fmaxf(w0, po) < wh;
        if (!bA && !bB) {
            dres = isR ? (a1 + 0.5f * w0) : (b1 - 0.5f * w0);
            wres = w0;
        } else {
            write = false;
            int L = atomicAdd(&s_cnt, 1);
            int fl = (type == 2 ? F_RLL : 0);
            s_task[L] = t;
            s_wp[L] = po; s_w0[L] = w0;
            s_p1[L] = a1; s_p2[L] = b1;
            int ns, base;
            if (bA) {
                s_whA[L] = wh;
                ns = 1;
                base = atomicAdd(&s_nslots, ns);
                s_desc[base] = (short)((L << 3) | 4);
            } else {
                fl |= F_HASB;
                bool sm = (wh <= SMALL_TH);
                if (sm) fl |= F_SMALL;
                s_whB[L] = wh;
                ns = sm ? 3 : 4;
                base = atomicAdd(&s_nslots, ns);
                for (int k = 0; k < ns; k++)
                    s_desc[base + k] = (short)((L << 3) | k);
            }
            s_flags[L] = fl;
        }
    } else if (type == 3) {
        if (pd >= fmaxf(wh1, wh2)) {
            dres = pd; wres = pd;
        } else {
            bool A1 = fmaxf(w0b, wh1) < pd, B1 = fmaxf(w0b, pd) < wh1;
            bool A2 = fmaxf(w0b, wh2) < pd, B2 = fmaxf(w0b, pd) < wh2;
            if (!(A1 | B1 | A2 | B2)) {
                float lwp = logf(fmaxf(pd, 1e-12f));
                bool pick1 = eps_val(w0b, wh1, lwp) <= eps_val(w0b, wh2, lwp);
                dres = pick1 ? (q1 + 0.5f * w0b) : (q2 + 0.5f * w0b);
                wres = w0b;
            } else {
                write = false;
                int L = atomicAdd(&s_cnt, 1);
                int fl = F_ISC;
                int sb = B1 ? 1 : (B2 ? 2 : 0);
                int sa = A1 ? 1 : (A2 ? 2 : 0);
                if (sb == 1) fl |= F_SB1; else if (sb == 2) fl |= F_SB2;
                if (sa == 1) fl |= F_SA1; else if (sa == 2) fl |= F_SA2;
                float whB = (sb == 1) ? wh1 : wh2;
                float whA = (sa == 1) ? wh1 : wh2;
                s_task[L] = t;
                s_wp[L] = pd; s_w0[L] = w0b;
                s_p1[L] = q1; s_p2[L] = q2;
                s_wh1[L] = wh1; s_wh2[L] = wh2;
                s_whA[L] = whA; s_whB[L] = whB;
                int nb = 0;
                bool sm = (whB <= SMALL_TH);
                if (sb) { fl |= F_HASB; if (sm) fl |= F_SMALL; nb = sm ? 3 : 4; }
                int ns = nb + (sa ? 1 : 0);
                int base = atomicAdd(&s_nslots, ns);
                for (int k = 0; k < nb; k++)
                    s_desc[base + k] = (short)((L << 3) | k);
                if (sa) s_desc[base + nb] = (short)((L << 3) | 4);
                s_flags[L] = fl;
            }
        }
    }
    if (write) {
        out[i * 4 + a]     = dres;
        out[i * 4 + 2 + a] = wres;
    }
    __syncthreads();

    // ------ phase 2a: endpoint short-circuit; compact survivors -----------
    int nslots = s_nslots;
    for (int sidx = tid; sidx < nslots; sidx += BLOCK) {
        int d = s_desc[sidx];
        int L = d >> 3, k = d & 7;
        float u, v, whS, wpc; bool sig;
        init_slot(k, s_wp[L], s_whB[L], s_whA[L], s_w0[L], u, v, whS, wpc, sig);
        float hi = E_F * wpc, lo = INV_E_F * wpc;
        float fu = bis_g(u, whS, wpc, hi, lo, sig);
        float fv = bis_g(v, whS, wpc, hi, lo, sig);
        if (fu >= 0.0f) {
            s_res[L * 5 + k] = u;               // reference: f(u0)>=0 -> u0
        } else if (fv <= 0.0f) {
            s_res[L * 5 + k] = v;               // reference: f(v0)<=0 -> v0
        } else {
            int j = atomicAdd(&s_cnt2, 1);
            s_it[j] = (short)d;                 // needs the bisection loop
        }
    }
    __syncthreads();

    // ------ phase 2b: dense bisection loops for survivors -----------------
    int cnt2 = s_cnt2;
    for (int j = tid; j < cnt2; j += BLOCK) {
        int d = s_it[j];
        int L = d >> 3, k = d & 7;
        float u, v, whS, wpc; bool sig;
        init_slot(k, s_wp[L], s_whB[L], s_whA[L], s_w0[L], u, v, whS, wpc, sig);
        float hi = E_F * wpc, lo = INV_E_F * wpc;
#pragma unroll 2
        for (int it = 0; it < BISECT_ITERS; it++) {
            float m = (u + v) * 0.5f;
            bool c = bis_g(m, whS, wpc, hi, lo, sig) >= 0.0f;
            v = c ? m : v;
            u = c ? u : m;
        }
        s_res[L * 5 + k] = (u + v) * 0.5f;      // fu<0<fv -> result is midpoint
    }
    __syncthreads();

    // ---------------- phase 3: finalize -----------------------------------
    int cnt = s_cnt;
    for (int L = tid; L < cnt; L += BLOCK) {
        int fl = s_flags[L];
        int tg2 = s_task[L];
        int ri = tg2 >> 1, ax = tg2 & 1;
        float wp = s_wp[L], w0s = s_w0[L];
        float lwp = logf(fmaxf(wp, 1e-12f));

        float bw = w0s;
        if (fl & F_HASB) {
            float whB = s_whB[L];
            bool sm = (fl & F_SMALL);
            float bv = eps_val(w0s, whB, lwp);
            float e1 = eps_val(whB, whB, lwp);
            if (e1 < bv) { bv = e1; bw = whB; }
            float e2 = eps_val(s_res[L * 5 + 0], whB, lwp);
            if (e2 < bv) { bv = e2; bw = s_res[L * 5 + 0]; }
            float e3 = eps_val(s_res[L * 5 + 1], whB, lwp);
            if (e3 < bv) { bv = e3; bw = s_res[L * 5 + 1]; }
            float e4 = eps_val(s_res[L * 5 + 2], whB, lwp);
            if (e4 < bv) { bv = e4; bw = s_res[L * 5 + 2]; }
            if (!sm) {
                float e5 = eps_val(s_res[L * 5 + 3], whB, lwp);
                if (e5 < bv) { bv = e5; bw = s_res[L * 5 + 3]; }
            }
        }

        float dr, wr;
        if (!(fl & F_ISC)) {
            wr = (fl & F_HASB) ? bw : s_res[L * 5 + 4];
            float aa1 = s_p1[L], bb1 = s_p2[L];
            dr = (fl & F_RLL) ? (bb1 - 0.5f * wr) : (aa1 + 0.5f * wr);
        } else {
            float a2 = s_p1[L], b2 = s_p2[L];
            float w1h = s_wh1[L], w2h = s_wh2[L];
            int sb = (fl & F_SB1) ? 1 : ((fl & F_SB2) ? 2 : 0);
            int sa = (fl & F_SA1) ? 1 : ((fl & F_SA2) ? 2 : 0);
            float wB = (fl & F_HASB) ? bw : w0s;
            float wA = sa ? s_res[L * 5 + 4] : w0s;
            float w1 = (sb == 1) ? wB : ((sa == 1) ? wA : w0s);
            float w2 = (sb == 2) ? wB : ((sa == 2) ? wA : w0s);
            bool pick1 = eps_val(w1, w1h, lwp) <= eps_val(w2, w2h, lwp);
            dr = pick1 ? (a2 + 0.5f * w1) : (b2 + 0.5f * w2);
            wr = pick1 ? w1 : w2;
        }
        out[ri * 4 + ax]     = dr;
        out[ri * 4 + 2 + ax] = wr;
    }
}

extern "C" void kernel_launch(void* const* d_in, const int* in_sizes, int n_in,
                              void* d_out, int out_size) {
    // metadata order: img, pred, target, crop_shapes, proposal_list, cases, ...
    const float* pred   = (const float*)d_in[1];
    const float* target = (const float*)d_in[2];
    const float* crop   = (const float*)d_in[3];
    const float* prop   = (const float*)d_in[4];
    const int*   cases  = (const int*)d_in[5];
    float* out = (float*)d_out;

    k_fused<<<TOTAL / BLOCK, BLOCK>>>(pred, target, crop, prop, cases, out);
}